// round 14
// baseline (speedup 1.0000x reference)
#include <cuda_runtime.h>
#include <cuda_bf16.h>
#include <math.h>
#include <stdint.h>

// Problem constants
#define BATCH   16
#define SEQ     1024
#define EMB     1024
#define NHEAD   16
#define DK      64
#define MROWS   (BATCH * SEQ)        // 16384

// Scratch (device globals; no allocation allowed)
__device__ __nv_bfloat16 g_xh[MROWS * EMB], g_xl[MROWS * EMB];
__device__ __nv_bfloat16 g_wqh[EMB * 3072], g_wql[EMB * 3072];
__device__ __nv_bfloat16 g_wfh[EMB * EMB],  g_wfl[EMB * EMB];
__device__ __nv_bfloat16 g_qh[BATCH * NHEAD * SEQ * DK], g_ql[BATCH * NHEAD * SEQ * DK];
__device__ __nv_bfloat16 g_kh[BATCH * NHEAD * SEQ * DK], g_kl[BATCH * NHEAD * SEQ * DK];
__device__ __nv_bfloat16 g_vh[BATCH * NHEAD * SEQ * DK], g_vl[BATCH * NHEAD * SEQ * DK];
__device__ __nv_bfloat16 g_ch[MROWS * EMB], g_cl[MROWS * EMB];

// ---------------------------------------------------------------------------
// PTX helpers
// ---------------------------------------------------------------------------
__device__ __forceinline__ uint32_t sm_u32(const void* p) {
    uint32_t a;
    asm("{ .reg .u64 t; cvta.to.shared.u64 t, %1; cvt.u32.u64 %0, t; }"
        : "=r"(a) : "l"(p));
    return a;
}
__device__ __forceinline__ void ldsm4(uint32_t addr, uint32_t* r) {
    asm volatile("ldmatrix.sync.aligned.m8n8.x4.shared.b16 {%0,%1,%2,%3}, [%4];"
                 : "=r"(r[0]), "=r"(r[1]), "=r"(r[2]), "=r"(r[3]) : "r"(addr));
}
__device__ __forceinline__ void ldsm4t(uint32_t addr, uint32_t* r) {
    asm volatile("ldmatrix.sync.aligned.m8n8.x4.trans.shared.b16 {%0,%1,%2,%3}, [%4];"
                 : "=r"(r[0]), "=r"(r[1]), "=r"(r[2]), "=r"(r[3]) : "r"(addr));
}
__device__ __forceinline__ void mma16816(float* d, const uint32_t* a, const uint32_t* b) {
    asm volatile(
        "mma.sync.aligned.m16n8k16.row.col.f32.bf16.bf16.f32 "
        "{%0,%1,%2,%3}, {%4,%5,%6,%7}, {%8,%9}, {%0,%1,%2,%3};"
        : "+f"(d[0]), "+f"(d[1]), "+f"(d[2]), "+f"(d[3])
        : "r"(a[0]), "r"(a[1]), "r"(a[2]), "r"(a[3]), "r"(b[0]), "r"(b[1]));
}
__device__ __forceinline__ void cpasync16(uint32_t dst, const void* src) {
    asm volatile("cp.async.cg.shared.global [%0], [%1], 16;" :: "r"(dst), "l"(src));
}
#define CP_COMMIT() asm volatile("cp.async.commit_group;" ::: "memory")
#define CP_WAIT(n)  asm volatile("cp.async.wait_group %0;" :: "n"(n) : "memory")

__device__ __forceinline__ uint32_t pack_bf2(float x, float y) {
    __nv_bfloat162 h = __floats2bfloat162_rn(x, y);
    return *(uint32_t*)&h;
}

// ---------------------------------------------------------------------------
// Pre-split: fp32 -> bf16 hi/lo planes.  which: 0=x 1=W_qkv 2=W_fc
// ---------------------------------------------------------------------------
__global__ __launch_bounds__(256) void split_f32(const float* __restrict__ src,
                                                 int which, int n4) {
    int i = blockIdx.x * 256 + threadIdx.x;
    if (i >= n4) return;
    __nv_bfloat16* hi = (which == 0) ? g_xh : (which == 1) ? g_wqh : g_wfh;
    __nv_bfloat16* lo = (which == 0) ? g_xl : (which == 1) ? g_wql : g_wfl;
    float4 v = __ldg((const float4*)src + i);
    __nv_bfloat162 h01 = __floats2bfloat162_rn(v.x, v.y);
    __nv_bfloat162 h23 = __floats2bfloat162_rn(v.z, v.w);
    __nv_bfloat162 l01 = __floats2bfloat162_rn(v.x - __bfloat162float(h01.x),
                                               v.y - __bfloat162float(h01.y));
    __nv_bfloat162 l23 = __floats2bfloat162_rn(v.z - __bfloat162float(h23.x),
                                               v.w - __bfloat162float(h23.y));
    *(uint2*)(hi + 4 * (size_t)i) = make_uint2(*(uint32_t*)&h01, *(uint32_t*)&h23);
    *(uint2*)(lo + 4 * (size_t)i) = make_uint2(*(uint32_t*)&l01, *(uint32_t*)&l23);
}

// ===========================================================================
// bf16-presplit GEMM: out[16384,N] = A @ W + bias.
// CTA tile 256x128, 512 threads (16 warps, warp=64x32), BK=32,
// 3-stage cp.async ring, ONE barrier per iteration.
// MODE 0: A=x-split, W=Wqkv-split (N=3072), scatter q/k/v hi/lo.
// MODE 1: A=ctx-split, W=Wfc-split (N=1024), fp32 out.
// ===========================================================================
#define SA_PITCH 80                 // 32 bf16 = 64B + 16 pad
#define SB_PITCH 272                // 128 bf16 = 256B + 16 pad
#define ST_AH 0
#define ST_AL (256 * SA_PITCH)              // 20480
#define ST_BH (2 * 256 * SA_PITCH)          // 40960
#define ST_BL (ST_BH + 32 * SB_PITCH)       // 49664
#define ST_SZ (ST_BL + 32 * SB_PITCH)       // 58368
#define G2_TOTAL (3 * ST_SZ)                // 175104

template <int MODE>
__global__ __launch_bounds__(512, 1) void gemm_bf(const float* __restrict__ bias,
                                                  float* __restrict__ out) {
    extern __shared__ char smem[];
    const uint32_t smb = sm_u32(smem);
    const int tid  = threadIdx.x;
    const int lane = tid & 31;
    const int wid  = tid >> 5;
    const int wm   = wid & 3;          // 4 m-blocks of 64
    const int wn   = wid >> 2;         // 4 n-blocks of 32
    const int mBase = blockIdx.y * 256;
    const int nBase = blockIdx.x * 128;
    const int ldW = (MODE == 0) ? 3072 : 1024;

    const __nv_bfloat16* Ah = (MODE == 0) ? g_xh : g_ch;
    const __nv_bfloat16* Al = (MODE == 0) ? g_xl : g_cl;
    const __nv_bfloat16* Bh = (MODE == 0) ? g_wqh : g_wfh;
    const __nv_bfloat16* Bl = (MODE == 0) ? g_wql : g_wfl;

    // acc[mt 4][nt 4][4]: 64 regs
    float acc[4][4][4];
#pragma unroll
    for (int i = 0; i < 4; i++)
#pragma unroll
        for (int j = 0; j < 4; j++)
#pragma unroll
            for (int q = 0; q < 4; q++) acc[i][j][q] = 0.f;

    // load one BK=32 stage: A 256x32 (hi+lo), B 32x128 (hi+lo)
    auto load_stage = [&](int stage, int kc) {
        const uint32_t sb = smb + stage * ST_SZ;
        const int kOff = kc * 32;
        // A: 256 rows x 4 x16B chunks per plane = 1024 cp/plane; 2/thread/plane
#pragma unroll
        for (int i = 0; i < 2; i++) {
            int idx = tid + i * 512;                 // 0..1023
            int r = idx >> 2, ch = idx & 3;
            const size_t go = (size_t)(mBase + r) * 1024 + kOff + ch * 8;
            cpasync16(sb + ST_AH + r * SA_PITCH + ch * 16, Ah + go);
            cpasync16(sb + ST_AL + r * SA_PITCH + ch * 16, Al + go);
        }
        // B: 32 rows x 16 x16B chunks per plane = 512 cp/plane; 1/thread/plane
        {
            int r = tid >> 4, ch = tid & 15;
            const size_t go = (size_t)(kOff + r) * ldW + nBase + ch * 8;
            cpasync16(sb + ST_BH + r * SB_PITCH + ch * 16, Bh + go);
            cpasync16(sb + ST_BL + r * SB_PITCH + ch * 16, Bl + go);
        }
        CP_COMMIT();
    };

    load_stage(0, 0);
    load_stage(1, 1);

    for (int c = 0; c < 32; c++) {
        const int st = c % 3;
        if (c < 31) { CP_WAIT(1); } else { CP_WAIT(0); }
        __syncthreads();                 // stage st visible; stage (c+2)%3 free
        if (c + 2 < 32) load_stage((c + 2) % 3, c + 2);

        const uint32_t sb = smb + st * ST_SZ;
#pragma unroll
        for (int ks = 0; ks < 2; ks++) {
            const int k0 = ks * 16;
            uint32_t Ahf[4][4], Alf[4][4];
#pragma unroll
            for (int mt = 0; mt < 4; mt++) {
                uint32_t addr = sb + (uint32_t)((wm * 64 + mt * 16 + (lane & 15)) * SA_PITCH
                                                + (k0 + (lane >> 4) * 8) * 2);
                ldsm4(addr + ST_AH, Ahf[mt]);
                ldsm4(addr + ST_AL, Alf[mt]);
            }
#pragma unroll
            for (int p = 0; p < 2; p++) {
                uint32_t addr = sb + (uint32_t)((k0 + (lane & 15)) * SB_PITCH
                                                + (wn * 32 + p * 16 + (lane >> 4) * 8) * 2);
                uint32_t r[4], bh_[2][2], bl_[2][2];
                ldsm4t(addr + ST_BH, r);
                bh_[0][0] = r[0]; bh_[0][1] = r[1];
                bh_[1][0] = r[2]; bh_[1][1] = r[3];
                ldsm4t(addr + ST_BL, r);
                bl_[0][0] = r[0]; bl_[0][1] = r[1];
                bl_[1][0] = r[2]; bl_[1][1] = r[3];
#pragma unroll
                for (int mt = 0; mt < 4; mt++)
#pragma unroll
                    for (int nt = 0; nt < 2; nt++) {
                        float* d = acc[mt][2 * p + nt];
                        mma16816(d, Ahf[mt], bh_[nt]);
                        mma16816(d, Ahf[mt], bl_[nt]);
                        mma16816(d, Alf[mt], bh_[nt]);
                    }
            }
        }
        // no trailing barrier: next iteration's barrier protects stage reuse
    }

    // ---- epilogue ----
    const int rbase = mBase + wm * 64 + (lane >> 2);
    const int cbase = nBase + wn * 32 + 2 * (lane & 3);
#pragma unroll
    for (int mt = 0; mt < 4; mt++) {
#pragma unroll
        for (int nt = 0; nt < 4; nt++) {
            const int col = cbase + nt * 8;
            const float bx = __ldg(&bias[col]);
            const float by = __ldg(&bias[col + 1]);
#pragma unroll
            for (int half = 0; half < 2; half++) {
                const int row = rbase + mt * 16 + half * 8;
                float vx = acc[mt][nt][half * 2 + 0] + bx;
                float vy = acc[mt][nt][half * 2 + 1] + by;
                if (MODE == 1) {
                    *(float2*)(out + (size_t)row * 1024 + col) = make_float2(vx, vy);
                } else {
                    const int which = col >> 10;
                    const int h = (col >> 6) & 15;
                    const int d0 = col & 63;
                    const int b = row >> 10;
                    const int n_tok = row & 1023;
                    size_t idx = ((size_t)(b * NHEAD + h) * SEQ + n_tok) * DK + d0;
                    __nv_bfloat16 hx = __float2bfloat16_rn(vx);
                    __nv_bfloat16 hy = __float2bfloat16_rn(vy);
                    __nv_bfloat162 hv = {hx, hy};
                    __nv_bfloat162 lv = {__float2bfloat16_rn(vx - __bfloat162float(hx)),
                                         __float2bfloat16_rn(vy - __bfloat162float(hy))};
                    __nv_bfloat16* dh = (which == 0) ? g_qh : (which == 1) ? g_kh : g_vh;
                    __nv_bfloat16* dl = (which == 0) ? g_ql : (which == 1) ? g_kl : g_vl;
                    *(__nv_bfloat162*)(dh + idx) = hv;
                    *(__nv_bfloat162*)(dl + idx) = lv;
                }
            }
        }
    }
}

// ===========================================================================
// Flash attention on tensor cores (unchanged).
// ===========================================================================
#define FA_PITCH  144
#define FA_QH     0
#define FA_QL     (128 * FA_PITCH)
#define FA_KV0    (2 * 128 * FA_PITCH)
#define FA_KVSZ   (4 * 64 * FA_PITCH)
#define FA_KH     0
#define FA_KL     (64 * FA_PITCH)
#define FA_VH     (2 * 64 * FA_PITCH)
#define FA_VL     (3 * 64 * FA_PITCH)
#define FA_TOTAL  (FA_KV0 + 2 * FA_KVSZ)       // 110592

__global__ __launch_bounds__(256, 1) void flash_attn_tc() {
    extern __shared__ char smem[];
    const uint32_t smb = sm_u32(smem);
    const int tid  = threadIdx.x;
    const int lane = tid & 31;
    const int wid  = tid >> 5;
    const int qtile = blockIdx.x;
    const int bh    = blockIdx.y;

    const size_t headOff = (size_t)bh * SEQ * DK;
    const __nv_bfloat16* Qh = g_qh + headOff + (size_t)qtile * 128 * DK;
    const __nv_bfloat16* Ql = g_ql + headOff + (size_t)qtile * 128 * DK;

    {
#pragma unroll
        for (int i = 0; i < 4; i++) {
            int idx = tid + i * 256;
            int r = idx >> 3, c16 = idx & 7;
            cpasync16(smb + FA_QH + r * FA_PITCH + c16 * 16, (const char*)Qh + r * 128 + c16 * 16);
            cpasync16(smb + FA_QL + r * FA_PITCH + c16 * 16, (const char*)Ql + r * 128 + c16 * 16);
        }
        const __nv_bfloat16* src[4] = {g_kh + headOff, g_kl + headOff,
                                       g_vh + headOff, g_vl + headOff};
#pragma unroll
        for (int t4 = 0; t4 < 4; t4++) {
#pragma unroll
            for (int i = 0; i < 2; i++) {
                int idx = tid + i * 256;
                int r = idx >> 3, c16 = idx & 7;
                cpasync16(smb + FA_KV0 + t4 * (64 * FA_PITCH) + r * FA_PITCH + c16 * 16,
                          (const char*)src[t4] + r * 128 + c16 * 16);
            }
        }
        CP_COMMIT();
    }

    uint32_t QHf[4][4], QLf[4][4];
    float S[8][4];
    float O[8][4];
    float m0 = -INFINITY, m1 = -INFINITY, l0 = 0.f, l1 = 0.f;
#pragma unroll
    for (int nt = 0; nt < 8; nt++)
#pragma unroll
        for (int j = 0; j < 4; j++) O[nt][j] = 0.f;

    const __nv_bfloat16* Kh = g_kh + headOff;
    const __nv_bfloat16* Kl = g_kl + headOff;
    const __nv_bfloat16* Vh = g_vh + headOff;
    const __nv_bfloat16* Vl = g_vl + headOff;

    for (int c = 0; c < 16; c++) {
        const uint32_t kv = smb + FA_KV0 + (c & 1) * FA_KVSZ;

        if (c > 0) __syncthreads();

        if (c + 1 < 16) {
            const uint32_t nkv = smb + FA_KV0 + ((c + 1) & 1) * FA_KVSZ;
            const int rowOff = (c + 1) * 64;
            const __nv_bfloat16* src[4] = {Kh, Kl, Vh, Vl};
#pragma unroll
            for (int t4 = 0; t4 < 4; t4++) {
#pragma unroll
                for (int i = 0; i < 2; i++) {
                    int idx = tid + i * 256;
                    int r = idx >> 3, c16 = idx & 7;
                    cpasync16(nkv + t4 * (64 * FA_PITCH) + r * FA_PITCH + c16 * 16,
                              (const char*)src[t4] + (size_t)(rowOff + r) * 128 + c16 * 16);
                }
            }
            CP_COMMIT();
            CP_WAIT(1);
        } else {
            CP_WAIT(0);
        }
        __syncthreads();

        if (c == 0) {
#pragma unroll
            for (int ks = 0; ks < 4; ks++) {
                uint32_t addr = smb + (uint32_t)((wid * 16 + (lane & 15)) * FA_PITCH
                                                 + (ks * 16 + (lane >> 4) * 8) * 2);
                ldsm4(addr + FA_QH, QHf[ks]);
                ldsm4(addr + FA_QL, QLf[ks]);
            }
        }

#pragma unroll
        for (int nt = 0; nt < 8; nt++)
#pragma unroll
            for (int j = 0; j < 4; j++) S[nt][j] = 0.f;

#pragma unroll
        for (int p = 0; p < 4; p++) {
            uint32_t bh_[4][2][2], bl_[4][2][2];
#pragma unroll
            for (int ks = 0; ks < 4; ks++) {
                uint32_t addr = kv + (uint32_t)((p * 16 + (lane & 15)) * FA_PITCH
                                                + (ks * 16 + (lane >> 4) * 8) * 2);
                uint32_t r[4];
                ldsm4(addr + FA_KH, r);
                bh_[ks][0][0] = r[0]; bh_[ks][0][1] = r[2];
                bh_[ks][1][0] = r[1]; bh_[ks][1][1] = r[3];
                ldsm4(addr + FA_KL, r);
                bl_[ks][0][0] = r[0]; bl_[ks][0][1] = r[2];
                bl_[ks][1][0] = r[1]; bl_[ks][1][1] = r[3];
            }
#pragma unroll
            for (int ks = 0; ks < 4; ks++) {
#pragma unroll
                for (int nt = 0; nt < 2; nt++) {
                    mma16816(S[2 * p + nt], QHf[ks], bh_[ks][nt]);
                    mma16816(S[2 * p + nt], QHf[ks], bl_[ks][nt]);
                    mma16816(S[2 * p + nt], QLf[ks], bh_[ks][nt]);
                }
            }
        }

        float mx0 = -INFINITY, mx1 = -INFINITY;
#pragma unroll
        for (int nt = 0; nt < 8; nt++) {
            S[nt][0] *= 0.125f; S[nt][1] *= 0.125f;
            S[nt][2] *= 0.125f; S[nt][3] *= 0.125f;
            mx0 = fmaxf(mx0, fmaxf(S[nt][0], S[nt][1]));
            mx1 = fmaxf(mx1, fmaxf(S[nt][2], S[nt][3]));
        }
        mx0 = fmaxf(mx0, __shfl_xor_sync(0xffffffffu, mx0, 1));
        mx0 = fmaxf(mx0, __shfl_xor_sync(0xffffffffu, mx0, 2));
        mx1 = fmaxf(mx1, __shfl_xor_sync(0xffffffffu, mx1, 1));
        mx1 = fmaxf(mx1, __shfl_xor_sync(0xffffffffu, mx1, 2));
        const float nm0 = fmaxf(m0, mx0), nm1 = fmaxf(m1, mx1);
        const float a0 = __expf(m0 - nm0), a1 = __expf(m1 - nm1);
        m0 = nm0; m1 = nm1;
        float s0 = 0.f, s1 = 0.f;
#pragma unroll
        for (int nt = 0; nt < 8; nt++) {
            S[nt][0] = __expf(S[nt][0] - nm0);
            S[nt][1] = __expf(S[nt][1] - nm0);
            S[nt][2] = __expf(S[nt][2] - nm1);
            S[nt][3] = __expf(S[nt][3] - nm1);
            s0 += S[nt][0] + S[nt][1];
            s1 += S[nt][2] + S[nt][3];
        }
        s0 += __shfl_xor_sync(0xffffffffu, s0, 1);
        s0 += __shfl_xor_sync(0xffffffffu, s0, 2);
        s1 += __shfl_xor_sync(0xffffffffu, s1, 1);
        s1 += __shfl_xor_sync(0xffffffffu, s1, 2);
        l0 = l0 * a0 + s0;
        l1 = l1 * a1 + s1;
#pragma unroll
        for (int nt = 0; nt < 8; nt++) {
            O[nt][0] *= a0; O[nt][1] *= a0;
            O[nt][2] *= a1; O[nt][3] *= a1;
        }

#pragma unroll
        for (int kt = 0; kt < 4; kt++) {
            uint32_t ah[4], al[4];
            {
                float e0 = S[2 * kt][0], e1 = S[2 * kt][1];
                float e2 = S[2 * kt][2], e3 = S[2 * kt][3];
                float f0 = S[2 * kt + 1][0], f1 = S[2 * kt + 1][1];
                float f2 = S[2 * kt + 1][2], f3 = S[2 * kt + 1][3];
                ah[0] = pack_bf2(e0, e1); ah[1] = pack_bf2(e2, e3);
                ah[2] = pack_bf2(f0, f1); ah[3] = pack_bf2(f2, f3);
                __nv_bfloat162* hp;
                hp = (__nv_bfloat162*)&ah[0];
                al[0] = pack_bf2(e0 - __bfloat162float(hp->x), e1 - __bfloat162float(hp->y));
                hp = (__nv_bfloat162*)&ah[1];
                al[1] = pack_bf2(e2 - __bfloat162float(hp->x), e3 - __bfloat162float(hp->y));
                hp = (__nv_bfloat162*)&ah[2];
                al[2] = pack_bf2(f0 - __bfloat162float(hp->x), f1 - __bfloat162float(hp->y));
                hp = (__nv_bfloat162*)&ah[3];
                al[3] = pack_bf2(f2 - __bfloat162float(hp->x), f3 - __bfloat162float(hp->y));
            }
#pragma unroll
            for (int p = 0; p < 4; p++) {
                uint32_t addr = kv + (uint32_t)((kt * 16 + (lane & 15)) * FA_PITCH
                                                + (p * 16 + (lane >> 4) * 8) * 2);
                uint32_t r[4], vh_[2][2], vl_[2][2];
                ldsm4t(addr + FA_VH, r);
                vh_[0][0] = r[0]; vh_[0][1] = r[1];
                vh_[1][0] = r[2]; vh_[1][1] = r[3];
                ldsm4t(addr + FA_VL, r);
                vl_[0][0] = r[0]; vl_[0][1] = r[1];
                vl_[1][0] = r[2]; vl_[1][1] = r[3];
#pragma unroll
                for (int nt = 0; nt < 2; nt++) {
                    mma16816(O[2 * p + nt], ah, vh_[nt]);
                    mma16816(O[2 * p + nt], ah, vl_[nt]);
                    mma16816(O[2 * p + nt], al, vh_[nt]);
                }
            }
        }
    }

    const int h = bh & 15;
    const int b = bh >> 4;
    const float i0 = 1.f / l0, i1 = 1.f / l1;
    const int r0 = qtile * 128 + wid * 16 + (lane >> 2);
    const int colb = h * 64 + 2 * (lane & 3);
#pragma unroll
    for (int nt = 0; nt < 8; nt++) {
        const int col = colb + nt * 8;
#pragma unroll
        for (int half = 0; half < 2; half++) {
            float vx = O[nt][half * 2 + 0] * (half ? i1 : i0);
            float vy = O[nt][half * 2 + 1] * (half ? i1 : i0);
            size_t idx = ((size_t)b * SEQ + r0 + half * 8) * EMB + col;
            __nv_bfloat16 hx = __float2bfloat16_rn(vx);
            __nv_bfloat16 hy = __float2bfloat16_rn(vy);
            __nv_bfloat162 hv = {hx, hy};
            __nv_bfloat162 lv = {__float2bfloat16_rn(vx - __bfloat162float(hx)),
                                 __float2bfloat16_rn(vy - __bfloat162float(hy))};
            *(__nv_bfloat162*)(g_ch + idx) = hv;
            *(__nv_bfloat162*)(g_cl + idx) = lv;
        }
    }
}

// ---------------------------------------------------------------------------
extern "C" void kernel_launch(void* const* d_in, const int* in_sizes, int n_in,
                              void* d_out, int out_size) {
    (void)in_sizes; (void)n_in; (void)out_size;
    const float* x     = (const float*)d_in[0];
    const float* W_qkv = (const float*)d_in[1];
    const float* b_qkv = (const float*)d_in[2];
    const float* W_fc  = (const float*)d_in[3];
    const float* b_fc  = (const float*)d_in[4];
    float* out = (float*)d_out;

    split_f32<<<(MROWS * EMB / 4 + 255) / 256, 256>>>(x, 0, MROWS * EMB / 4);
    split_f32<<<(EMB * 3072 / 4 + 255) / 256, 256>>>(W_qkv, 1, EMB * 3072 / 4);
    split_f32<<<(EMB * EMB / 4 + 255) / 256, 256>>>(W_fc, 2, EMB * EMB / 4);

    {
        cudaFuncSetAttribute(gemm_bf<0>, cudaFuncAttributeMaxDynamicSharedMemorySize, G2_TOTAL);
        dim3 grid(3072 / 128, MROWS / 256);
        gemm_bf<0><<<grid, 512, G2_TOTAL>>>(b_qkv, nullptr);
    }
    {
        cudaFuncSetAttribute(flash_attn_tc, cudaFuncAttributeMaxDynamicSharedMemorySize, FA_TOTAL);
        dim3 grid(SEQ / 128, BATCH * NHEAD);
        flash_attn_tc<<<grid, 256, FA_TOTAL>>>();
    }
    {
        cudaFuncSetAttribute(gemm_bf<1>, cudaFuncAttributeMaxDynamicSharedMemorySize, G2_TOTAL);
        dim3 grid(1024 / 128, MROWS / 256);
        gemm_bf<1><<<grid, 512, G2_TOTAL>>>(b_fc, out);
    }
}

// round 15
// speedup vs baseline: 1.5062x; 1.5062x over previous
#include <cuda_runtime.h>
#include <cuda_bf16.h>
#include <math.h>
#include <stdint.h>

// Problem constants
#define BATCH   16
#define SEQ     1024
#define EMB     1024
#define NHEAD   16
#define DK      64
#define MROWS   (BATCH * SEQ)        // 16384

// Scratch (device globals; no allocation allowed)
__device__ __nv_bfloat16 g_xh[MROWS * EMB], g_xl[MROWS * EMB];
__device__ __nv_bfloat16 g_wqh[EMB * 3072], g_wql[EMB * 3072];
__device__ __nv_bfloat16 g_wfh[EMB * EMB],  g_wfl[EMB * EMB];
__device__ __nv_bfloat16 g_qh[BATCH * NHEAD * SEQ * DK], g_ql[BATCH * NHEAD * SEQ * DK];
__device__ __nv_bfloat16 g_kh[BATCH * NHEAD * SEQ * DK], g_kl[BATCH * NHEAD * SEQ * DK];
__device__ __nv_bfloat16 g_vh[BATCH * NHEAD * SEQ * DK], g_vl[BATCH * NHEAD * SEQ * DK];
__device__ __nv_bfloat16 g_ch[MROWS * EMB], g_cl[MROWS * EMB];

// ---------------------------------------------------------------------------
// PTX helpers
// ---------------------------------------------------------------------------
__device__ __forceinline__ uint32_t sm_u32(const void* p) {
    uint32_t a;
    asm("{ .reg .u64 t; cvta.to.shared.u64 t, %1; cvt.u32.u64 %0, t; }"
        : "=r"(a) : "l"(p));
    return a;
}
__device__ __forceinline__ void ldsm4(uint32_t addr, uint32_t* r) {
    asm volatile("ldmatrix.sync.aligned.m8n8.x4.shared.b16 {%0,%1,%2,%3}, [%4];"
                 : "=r"(r[0]), "=r"(r[1]), "=r"(r[2]), "=r"(r[3]) : "r"(addr));
}
__device__ __forceinline__ void ldsm4t(uint32_t addr, uint32_t* r) {
    asm volatile("ldmatrix.sync.aligned.m8n8.x4.trans.shared.b16 {%0,%1,%2,%3}, [%4];"
                 : "=r"(r[0]), "=r"(r[1]), "=r"(r[2]), "=r"(r[3]) : "r"(addr));
}
__device__ __forceinline__ void mma16816(float* d, const uint32_t* a, const uint32_t* b) {
    asm volatile(
        "mma.sync.aligned.m16n8k16.row.col.f32.bf16.bf16.f32 "
        "{%0,%1,%2,%3}, {%4,%5,%6,%7}, {%8,%9}, {%0,%1,%2,%3};"
        : "+f"(d[0]), "+f"(d[1]), "+f"(d[2]), "+f"(d[3])
        : "r"(a[0]), "r"(a[1]), "r"(a[2]), "r"(a[3]), "r"(b[0]), "r"(b[1]));
}
__device__ __forceinline__ void cpasync16(uint32_t dst, const void* src) {
    asm volatile("cp.async.cg.shared.global [%0], [%1], 16;" :: "r"(dst), "l"(src));
}
#define CP_COMMIT() asm volatile("cp.async.commit_group;" ::: "memory")
#define CP_WAIT(n)  asm volatile("cp.async.wait_group %0;" :: "n"(n) : "memory")

__device__ __forceinline__ uint32_t pack_bf2(float x, float y) {
    __nv_bfloat162 h = __floats2bfloat162_rn(x, y);
    return *(uint32_t*)&h;
}

// ---------------------------------------------------------------------------
// Pre-split: fp32 -> bf16 hi/lo planes.  which: 0=x 1=W_qkv 2=W_fc
// ---------------------------------------------------------------------------
__global__ __launch_bounds__(256) void split_f32(const float* __restrict__ src,
                                                 int which, int n4) {
    int i = blockIdx.x * 256 + threadIdx.x;
    if (i >= n4) return;
    __nv_bfloat16* hi = (which == 0) ? g_xh : (which == 1) ? g_wqh : g_wfh;
    __nv_bfloat16* lo = (which == 0) ? g_xl : (which == 1) ? g_wql : g_wfl;
    float4 v = __ldg((const float4*)src + i);
    __nv_bfloat162 h01 = __floats2bfloat162_rn(v.x, v.y);
    __nv_bfloat162 h23 = __floats2bfloat162_rn(v.z, v.w);
    __nv_bfloat162 l01 = __floats2bfloat162_rn(v.x - __bfloat162float(h01.x),
                                               v.y - __bfloat162float(h01.y));
    __nv_bfloat162 l23 = __floats2bfloat162_rn(v.z - __bfloat162float(h23.x),
                                               v.w - __bfloat162float(h23.y));
    *(uint2*)(hi + 4 * (size_t)i) = make_uint2(*(uint32_t*)&h01, *(uint32_t*)&h23);
    *(uint2*)(lo + 4 * (size_t)i) = make_uint2(*(uint32_t*)&l01, *(uint32_t*)&l23);
}

// ===========================================================================
// bf16-presplit GEMM: out[16384,N] = A @ W + bias.
// CTA tile 128x128, 512 threads (16 warps, warp=32x32 -> acc 32 regs),
// BK=64, 3-stage cp.async ring, ONE barrier per iteration.
// MODE 0: A=x-split, W=Wqkv-split (N=3072), scatter q/k/v hi/lo.
// MODE 1: A=ctx-split, W=Wfc-split (N=1024), fp32 out.
// ===========================================================================
#define SA_PITCH 144                // 64 bf16 = 128B + 16 pad
#define SB_PITCH 272                // 128 bf16 = 256B + 16 pad
#define ST_AH 0
#define ST_AL (128 * SA_PITCH)              // 18432
#define ST_BH (2 * 128 * SA_PITCH)          // 36864
#define ST_BL (ST_BH + 64 * SB_PITCH)       // 54272
#define ST_SZ (ST_BL + 64 * SB_PITCH)       // 71680
#define G2_TOTAL (3 * ST_SZ)                // 215040

template <int MODE>
__global__ __launch_bounds__(512, 1) void gemm_bf(const float* __restrict__ bias,
                                                  float* __restrict__ out) {
    extern __shared__ char smem[];
    const uint32_t smb = sm_u32(smem);
    const int tid  = threadIdx.x;
    const int lane = tid & 31;
    const int wid  = tid >> 5;
    const int wm   = wid & 3;          // 4 m-blocks of 32
    const int wn   = wid >> 2;         // 4 n-blocks of 32
    const int mBase = blockIdx.y * 128;
    const int nBase = blockIdx.x * 128;
    const int ldW = (MODE == 0) ? 3072 : 1024;

    const __nv_bfloat16* Ah = (MODE == 0) ? g_xh : g_ch;
    const __nv_bfloat16* Al = (MODE == 0) ? g_xl : g_cl;
    const __nv_bfloat16* Bh = (MODE == 0) ? g_wqh : g_wfh;
    const __nv_bfloat16* Bl = (MODE == 0) ? g_wql : g_wfl;

    // acc[mt 2][nt 4][4]: 32 regs
    float acc[2][4][4];
#pragma unroll
    for (int i = 0; i < 2; i++)
#pragma unroll
        for (int j = 0; j < 4; j++)
#pragma unroll
            for (int q = 0; q < 4; q++) acc[i][j][q] = 0.f;

    // load one BK=64 stage: A 128x64 (hi+lo), B 64x128 (hi+lo); 8 cp/thread
    auto load_stage = [&](int stage, int kc) {
        const uint32_t sb = smb + stage * ST_SZ;
        const int kOff = kc * 64;
        // A: 128 rows x 8 x16B chunks per plane = 1024 cp/plane; 2/thread/plane
#pragma unroll
        for (int i = 0; i < 2; i++) {
            int idx = tid + i * 512;                 // 0..1023
            int r = idx >> 3, ch = idx & 7;
            const size_t go = (size_t)(mBase + r) * 1024 + kOff + ch * 8;
            cpasync16(sb + ST_AH + r * SA_PITCH + ch * 16, Ah + go);
            cpasync16(sb + ST_AL + r * SA_PITCH + ch * 16, Al + go);
        }
        // B: 64 rows x 16 x16B chunks per plane = 1024 cp/plane; 2/thread/plane
#pragma unroll
        for (int i = 0; i < 2; i++) {
            int idx = tid + i * 512;                 // 0..1023
            int r = idx >> 4, ch = idx & 15;
            const size_t go = (size_t)(kOff + r) * ldW + nBase + ch * 8;
            cpasync16(sb + ST_BH + r * SB_PITCH + ch * 16, Bh + go);
            cpasync16(sb + ST_BL + r * SB_PITCH + ch * 16, Bl + go);
        }
        CP_COMMIT();
    };

    load_stage(0, 0);
    load_stage(1, 1);

    for (int c = 0; c < 16; c++) {
        const int st = c % 3;
        if (c < 15) { CP_WAIT(1); } else { CP_WAIT(0); }
        __syncthreads();                 // stage st visible; stage (c+2)%3 free
        if (c + 2 < 16) load_stage((c + 2) % 3, c + 2);

        const uint32_t sb = smb + st * ST_SZ;
#pragma unroll
        for (int ks = 0; ks < 4; ks++) {
            const int k0 = ks * 16;
            uint32_t Ahf[2][4], Alf[2][4];
#pragma unroll
            for (int mt = 0; mt < 2; mt++) {
                uint32_t addr = sb + (uint32_t)((wm * 32 + mt * 16 + (lane & 15)) * SA_PITCH
                                                + (k0 + (lane >> 4) * 8) * 2);
                ldsm4(addr + ST_AH, Ahf[mt]);
                ldsm4(addr + ST_AL, Alf[mt]);
            }
#pragma unroll
            for (int p = 0; p < 2; p++) {
                uint32_t addr = sb + (uint32_t)((k0 + (lane & 15)) * SB_PITCH
                                                + (wn * 32 + p * 16 + (lane >> 4) * 8) * 2);
                uint32_t r[4], bh_[2][2], bl_[2][2];
                ldsm4t(addr + ST_BH, r);
                bh_[0][0] = r[0]; bh_[0][1] = r[1];
                bh_[1][0] = r[2]; bh_[1][1] = r[3];
                ldsm4t(addr + ST_BL, r);
                bl_[0][0] = r[0]; bl_[0][1] = r[1];
                bl_[1][0] = r[2]; bl_[1][1] = r[3];
#pragma unroll
                for (int mt = 0; mt < 2; mt++)
#pragma unroll
                    for (int nt = 0; nt < 2; nt++) {
                        float* d = acc[mt][2 * p + nt];
                        mma16816(d, Ahf[mt], bh_[nt]);
                        mma16816(d, Ahf[mt], bl_[nt]);
                        mma16816(d, Alf[mt], bh_[nt]);
                    }
            }
        }
        // no trailing barrier: next iteration's barrier protects stage reuse
    }

    // ---- epilogue ----
    const int rbase = mBase + wm * 32 + (lane >> 2);
    const int cbase = nBase + wn * 32 + 2 * (lane & 3);
#pragma unroll
    for (int mt = 0; mt < 2; mt++) {
#pragma unroll
        for (int nt = 0; nt < 4; nt++) {
            const int col = cbase + nt * 8;
            const float bx = __ldg(&bias[col]);
            const float by = __ldg(&bias[col + 1]);
#pragma unroll
            for (int half = 0; half < 2; half++) {
                const int row = rbase + mt * 16 + half * 8;
                float vx = acc[mt][nt][half * 2 + 0] + bx;
                float vy = acc[mt][nt][half * 2 + 1] + by;
                if (MODE == 1) {
                    *(float2*)(out + (size_t)row * 1024 + col) = make_float2(vx, vy);
                } else {
                    const int which = col >> 10;
                    const int h = (col >> 6) & 15;
                    const int d0 = col & 63;
                    const int b = row >> 10;
                    const int n_tok = row & 1023;
                    size_t idx = ((size_t)(b * NHEAD + h) * SEQ + n_tok) * DK + d0;
                    __nv_bfloat16 hx = __float2bfloat16_rn(vx);
                    __nv_bfloat16 hy = __float2bfloat16_rn(vy);
                    __nv_bfloat162 hv = {hx, hy};
                    __nv_bfloat162 lv = {__float2bfloat16_rn(vx - __bfloat162float(hx)),
                                         __float2bfloat16_rn(vy - __bfloat162float(hy))};
                    __nv_bfloat16* dh = (which == 0) ? g_qh : (which == 1) ? g_kh : g_vh;
                    __nv_bfloat16* dl = (which == 0) ? g_ql : (which == 1) ? g_kl : g_vl;
                    *(__nv_bfloat162*)(dh + idx) = hv;
                    *(__nv_bfloat162*)(dl + idx) = lv;
                }
            }
        }
    }
}

// ===========================================================================
// Flash attention on tensor cores (unchanged).
// ===========================================================================
#define FA_PITCH  144
#define FA_QH     0
#define FA_QL     (128 * FA_PITCH)
#define FA_KV0    (2 * 128 * FA_PITCH)
#define FA_KVSZ   (4 * 64 * FA_PITCH)
#define FA_KH     0
#define FA_KL     (64 * FA_PITCH)
#define FA_VH     (2 * 64 * FA_PITCH)
#define FA_VL     (3 * 64 * FA_PITCH)
#define FA_TOTAL  (FA_KV0 + 2 * FA_KVSZ)       // 110592

__global__ __launch_bounds__(256, 1) void flash_attn_tc() {
    extern __shared__ char smem[];
    const uint32_t smb = sm_u32(smem);
    const int tid  = threadIdx.x;
    const int lane = tid & 31;
    const int wid  = tid >> 5;
    const int qtile = blockIdx.x;
    const int bh    = blockIdx.y;

    const size_t headOff = (size_t)bh * SEQ * DK;
    const __nv_bfloat16* Qh = g_qh + headOff + (size_t)qtile * 128 * DK;
    const __nv_bfloat16* Ql = g_ql + headOff + (size_t)qtile * 128 * DK;

    {
#pragma unroll
        for (int i = 0; i < 4; i++) {
            int idx = tid + i * 256;
            int r = idx >> 3, c16 = idx & 7;
            cpasync16(smb + FA_QH + r * FA_PITCH + c16 * 16, (const char*)Qh + r * 128 + c16 * 16);
            cpasync16(smb + FA_QL + r * FA_PITCH + c16 * 16, (const char*)Ql + r * 128 + c16 * 16);
        }
        const __nv_bfloat16* src[4] = {g_kh + headOff, g_kl + headOff,
                                       g_vh + headOff, g_vl + headOff};
#pragma unroll
        for (int t4 = 0; t4 < 4; t4++) {
#pragma unroll
            for (int i = 0; i < 2; i++) {
                int idx = tid + i * 256;
                int r = idx >> 3, c16 = idx & 7;
                cpasync16(smb + FA_KV0 + t4 * (64 * FA_PITCH) + r * FA_PITCH + c16 * 16,
                          (const char*)src[t4] + r * 128 + c16 * 16);
            }
        }
        CP_COMMIT();
    }

    uint32_t QHf[4][4], QLf[4][4];
    float S[8][4];
    float O[8][4];
    float m0 = -INFINITY, m1 = -INFINITY, l0 = 0.f, l1 = 0.f;
#pragma unroll
    for (int nt = 0; nt < 8; nt++)
#pragma unroll
        for (int j = 0; j < 4; j++) O[nt][j] = 0.f;

    const __nv_bfloat16* Kh = g_kh + headOff;
    const __nv_bfloat16* Kl = g_kl + headOff;
    const __nv_bfloat16* Vh = g_vh + headOff;
    const __nv_bfloat16* Vl = g_vl + headOff;

    for (int c = 0; c < 16; c++) {
        const uint32_t kv = smb + FA_KV0 + (c & 1) * FA_KVSZ;

        if (c > 0) __syncthreads();

        if (c + 1 < 16) {
            const uint32_t nkv = smb + FA_KV0 + ((c + 1) & 1) * FA_KVSZ;
            const int rowOff = (c + 1) * 64;
            const __nv_bfloat16* src[4] = {Kh, Kl, Vh, Vl};
#pragma unroll
            for (int t4 = 0; t4 < 4; t4++) {
#pragma unroll
                for (int i = 0; i < 2; i++) {
                    int idx = tid + i * 256;
                    int r = idx >> 3, c16 = idx & 7;
                    cpasync16(nkv + t4 * (64 * FA_PITCH) + r * FA_PITCH + c16 * 16,
                              (const char*)src[t4] + (size_t)(rowOff + r) * 128 + c16 * 16);
                }
            }
            CP_COMMIT();
            CP_WAIT(1);
        } else {
            CP_WAIT(0);
        }
        __syncthreads();

        if (c == 0) {
#pragma unroll
            for (int ks = 0; ks < 4; ks++) {
                uint32_t addr = smb + (uint32_t)((wid * 16 + (lane & 15)) * FA_PITCH
                                                 + (ks * 16 + (lane >> 4) * 8) * 2);
                ldsm4(addr + FA_QH, QHf[ks]);
                ldsm4(addr + FA_QL, QLf[ks]);
            }
        }

#pragma unroll
        for (int nt = 0; nt < 8; nt++)
#pragma unroll
            for (int j = 0; j < 4; j++) S[nt][j] = 0.f;

#pragma unroll
        for (int p = 0; p < 4; p++) {
            uint32_t bh_[4][2][2], bl_[4][2][2];
#pragma unroll
            for (int ks = 0; ks < 4; ks++) {
                uint32_t addr = kv + (uint32_t)((p * 16 + (lane & 15)) * FA_PITCH
                                                + (ks * 16 + (lane >> 4) * 8) * 2);
                uint32_t r[4];
                ldsm4(addr + FA_KH, r);
                bh_[ks][0][0] = r[0]; bh_[ks][0][1] = r[2];
                bh_[ks][1][0] = r[1]; bh_[ks][1][1] = r[3];
                ldsm4(addr + FA_KL, r);
                bl_[ks][0][0] = r[0]; bl_[ks][0][1] = r[2];
                bl_[ks][1][0] = r[1]; bl_[ks][1][1] = r[3];
            }
#pragma unroll
            for (int ks = 0; ks < 4; ks++) {
#pragma unroll
                for (int nt = 0; nt < 2; nt++) {
                    mma16816(S[2 * p + nt], QHf[ks], bh_[ks][nt]);
                    mma16816(S[2 * p + nt], QHf[ks], bl_[ks][nt]);
                    mma16816(S[2 * p + nt], QLf[ks], bh_[ks][nt]);
                }
            }
        }

        float mx0 = -INFINITY, mx1 = -INFINITY;
#pragma unroll
        for (int nt = 0; nt < 8; nt++) {
            S[nt][0] *= 0.125f; S[nt][1] *= 0.125f;
            S[nt][2] *= 0.125f; S[nt][3] *= 0.125f;
            mx0 = fmaxf(mx0, fmaxf(S[nt][0], S[nt][1]));
            mx1 = fmaxf(mx1, fmaxf(S[nt][2], S[nt][3]));
        }
        mx0 = fmaxf(mx0, __shfl_xor_sync(0xffffffffu, mx0, 1));
        mx0 = fmaxf(mx0, __shfl_xor_sync(0xffffffffu, mx0, 2));
        mx1 = fmaxf(mx1, __shfl_xor_sync(0xffffffffu, mx1, 1));
        mx1 = fmaxf(mx1, __shfl_xor_sync(0xffffffffu, mx1, 2));
        const float nm0 = fmaxf(m0, mx0), nm1 = fmaxf(m1, mx1);
        const float a0 = __expf(m0 - nm0), a1 = __expf(m1 - nm1);
        m0 = nm0; m1 = nm1;
        float s0 = 0.f, s1 = 0.f;
#pragma unroll
        for (int nt = 0; nt < 8; nt++) {
            S[nt][0] = __expf(S[nt][0] - nm0);
            S[nt][1] = __expf(S[nt][1] - nm0);
            S[nt][2] = __expf(S[nt][2] - nm1);
            S[nt][3] = __expf(S[nt][3] - nm1);
            s0 += S[nt][0] + S[nt][1];
            s1 += S[nt][2] + S[nt][3];
        }
        s0 += __shfl_xor_sync(0xffffffffu, s0, 1);
        s0 += __shfl_xor_sync(0xffffffffu, s0, 2);
        s1 += __shfl_xor_sync(0xffffffffu, s1, 1);
        s1 += __shfl_xor_sync(0xffffffffu, s1, 2);
        l0 = l0 * a0 + s0;
        l1 = l1 * a1 + s1;
#pragma unroll
        for (int nt = 0; nt < 8; nt++) {
            O[nt][0] *= a0; O[nt][1] *= a0;
            O[nt][2] *= a1; O[nt][3] *= a1;
        }

#pragma unroll
        for (int kt = 0; kt < 4; kt++) {
            uint32_t ah[4], al[4];
            {
                float e0 = S[2 * kt][0], e1 = S[2 * kt][1];
                float e2 = S[2 * kt][2], e3 = S[2 * kt][3];
                float f0 = S[2 * kt + 1][0], f1 = S[2 * kt + 1][1];
                float f2 = S[2 * kt + 1][2], f3 = S[2 * kt + 1][3];
                ah[0] = pack_bf2(e0, e1); ah[1] = pack_bf2(e2, e3);
                ah[2] = pack_bf2(f0, f1); ah[3] = pack_bf2(f2, f3);
                __nv_bfloat162* hp;
                hp = (__nv_bfloat162*)&ah[0];
                al[0] = pack_bf2(e0 - __bfloat162float(hp->x), e1 - __bfloat162float(hp->y));
                hp = (__nv_bfloat162*)&ah[1];
                al[1] = pack_bf2(e2 - __bfloat162float(hp->x), e3 - __bfloat162float(hp->y));
                hp = (__nv_bfloat162*)&ah[2];
                al[2] = pack_bf2(f0 - __bfloat162float(hp->x), f1 - __bfloat162float(hp->y));
                hp = (__nv_bfloat162*)&ah[3];
                al[3] = pack_bf2(f2 - __bfloat162float(hp->x), f3 - __bfloat162float(hp->y));
            }
#pragma unroll
            for (int p = 0; p < 4; p++) {
                uint32_t addr = kv + (uint32_t)((kt * 16 + (lane & 15)) * FA_PITCH
                                                + (p * 16 + (lane >> 4) * 8) * 2);
                uint32_t r[4], vh_[2][2], vl_[2][2];
                ldsm4t(addr + FA_VH, r);
                vh_[0][0] = r[0]; vh_[0][1] = r[1];
                vh_[1][0] = r[2]; vh_[1][1] = r[3];
                ldsm4t(addr + FA_VL, r);
                vl_[0][0] = r[0]; vl_[0][1] = r[1];
                vl_[1][0] = r[2]; vl_[1][1] = r[3];
#pragma unroll
                for (int nt = 0; nt < 2; nt++) {
                    mma16816(O[2 * p + nt], ah, vh_[nt]);
                    mma16816(O[2 * p + nt], ah, vl_[nt]);
                    mma16816(O[2 * p + nt], al, vh_[nt]);
                }
            }
        }
    }

    const int h = bh & 15;
    const int b = bh >> 4;
    const float i0 = 1.f / l0, i1 = 1.f / l1;
    const int r0 = qtile * 128 + wid * 16 + (lane >> 2);
    const int colb = h * 64 + 2 * (lane & 3);
#pragma unroll
    for (int nt = 0; nt < 8; nt++) {
        const int col = colb + nt * 8;
#pragma unroll
        for (int half = 0; half < 2; half++) {
            float vx = O[nt][half * 2 + 0] * (half ? i1 : i0);
            float vy = O[nt][half * 2 + 1] * (half ? i1 : i0);
            size_t idx = ((size_t)b * SEQ + r0 + half * 8) * EMB + col;
            __nv_bfloat16 hx = __float2bfloat16_rn(vx);
            __nv_bfloat16 hy = __float2bfloat16_rn(vy);
            __nv_bfloat162 hv = {hx, hy};
            __nv_bfloat162 lv = {__float2bfloat16_rn(vx - __bfloat162float(hx)),
                                 __float2bfloat16_rn(vy - __bfloat162float(hy))};
            *(__nv_bfloat162*)(g_ch + idx) = hv;
            *(__nv_bfloat162*)(g_cl + idx) = lv;
        }
    }
}

// ---------------------------------------------------------------------------
extern "C" void kernel_launch(void* const* d_in, const int* in_sizes, int n_in,
                              void* d_out, int out_size) {
    (void)in_sizes; (void)n_in; (void)out_size;
    const float* x     = (const float*)d_in[0];
    const float* W_qkv = (const float*)d_in[1];
    const float* b_qkv = (const float*)d_in[2];
    const float* W_fc  = (const float*)d_in[3];
    const float* b_fc  = (const float*)d_in[4];
    float* out = (float*)d_out;

    split_f32<<<(MROWS * EMB / 4 + 255) / 256, 256>>>(x, 0, MROWS * EMB / 4);
    split_f32<<<(EMB * 3072 / 4 + 255) / 256, 256>>>(W_qkv, 1, EMB * 3072 / 4);
    split_f32<<<(EMB * EMB / 4 + 255) / 256, 256>>>(W_fc, 2, EMB * EMB / 4);

    {
        cudaFuncSetAttribute(gemm_bf<0>, cudaFuncAttributeMaxDynamicSharedMemorySize, G2_TOTAL);
        dim3 grid(3072 / 128, MROWS / 128);
        gemm_bf<0><<<grid, 512, G2_TOTAL>>>(b_qkv, nullptr);
    }
    {
        cudaFuncSetAttribute(flash_attn_tc, cudaFuncAttributeMaxDynamicSharedMemorySize, FA_TOTAL);
        dim3 grid(SEQ / 128, BATCH * NHEAD);
        flash_attn_tc<<<grid, 256, FA_TOTAL>>>();
    }
    {
        cudaFuncSetAttribute(gemm_bf<1>, cudaFuncAttributeMaxDynamicSharedMemorySize, G2_TOTAL);
        dim3 grid(1024 / 128, MROWS / 128);
        gemm_bf<1><<<grid, 512, G2_TOTAL>>>(b_fc, out);
    }
}

// round 17
// speedup vs baseline: 2.1096x; 1.4006x over previous
#include <cuda_runtime.h>
#include <cuda_fp16.h>
#include <math.h>
#include <stdint.h>

// Problem constants
#define BATCH   16
#define SEQ     1024
#define EMB     1024
#define NHEAD   16
#define DK      64
#define MROWS   (BATCH * SEQ)        // 16384

// Scratch (device globals).  fp16 two-term scheme:
//   A-side operands keep hi+lo planes (exact to 2^-22); B-side operands hi only.
__device__ __half g_xh[MROWS * EMB], g_xl[MROWS * EMB];    // x (A of QKV)
__device__ __half g_wqh[EMB * 3072];                       // W_qkv (B, hi only)
__device__ __half g_wfh[EMB * EMB];                        // W_fc  (B, hi only)
__device__ __half g_qh[BATCH * NHEAD * SEQ * DK], g_ql[BATCH * NHEAD * SEQ * DK];
__device__ __half g_kh[BATCH * NHEAD * SEQ * DK];          // K (B of QK, hi only)
__device__ __half g_vh[BATCH * NHEAD * SEQ * DK];          // V (B of PV, hi only)
__device__ __half g_ch[MROWS * EMB], g_cl[MROWS * EMB];    // ctx (A of FC)

// ---------------------------------------------------------------------------
// PTX helpers
// ---------------------------------------------------------------------------
__device__ __forceinline__ uint32_t sm_u32(const void* p) {
    uint32_t a;
    asm("{ .reg .u64 t; cvta.to.shared.u64 t, %1; cvt.u32.u64 %0, t; }"
        : "=r"(a) : "l"(p));
    return a;
}
__device__ __forceinline__ void ldsm4(uint32_t addr, uint32_t* r) {
    asm volatile("ldmatrix.sync.aligned.m8n8.x4.shared.b16 {%0,%1,%2,%3}, [%4];"
                 : "=r"(r[0]), "=r"(r[1]), "=r"(r[2]), "=r"(r[3]) : "r"(addr));
}
__device__ __forceinline__ void ldsm4t(uint32_t addr, uint32_t* r) {
    asm volatile("ldmatrix.sync.aligned.m8n8.x4.trans.shared.b16 {%0,%1,%2,%3}, [%4];"
                 : "=r"(r[0]), "=r"(r[1]), "=r"(r[2]), "=r"(r[3]) : "r"(addr));
}
__device__ __forceinline__ void mma16816(float* d, const uint32_t* a, const uint32_t* b) {
    asm volatile(
        "mma.sync.aligned.m16n8k16.row.col.f32.f16.f16.f32 "
        "{%0,%1,%2,%3}, {%4,%5,%6,%7}, {%8,%9}, {%0,%1,%2,%3};"
        : "+f"(d[0]), "+f"(d[1]), "+f"(d[2]), "+f"(d[3])
        : "r"(a[0]), "r"(a[1]), "r"(a[2]), "r"(a[3]), "r"(b[0]), "r"(b[1]));
}
__device__ __forceinline__ void cpasync16(uint32_t dst, const void* src) {
    asm volatile("cp.async.cg.shared.global [%0], [%1], 16;" :: "r"(dst), "l"(src));
}
#define CP_COMMIT() asm volatile("cp.async.commit_group;" ::: "memory")
#define CP_WAIT(n)  asm volatile("cp.async.wait_group %0;" :: "n"(n) : "memory")

__device__ __forceinline__ uint32_t pack_h2(float x, float y) {
    __half2 h = __floats2half2_rn(x, y);
    return *(uint32_t*)&h;
}

// ---------------------------------------------------------------------------
// Pre-split: fp32 -> fp16.  which 0: x -> hi+lo planes.  1: Wqkv hi.  2: Wfc hi.
// ---------------------------------------------------------------------------
__global__ __launch_bounds__(256) void split_f32(const float* __restrict__ src,
                                                 int which, int n4) {
    int i = blockIdx.x * 256 + threadIdx.x;
    if (i >= n4) return;
    float4 v = __ldg((const float4*)src + i);
    if (which == 0) {
        __half hx = __float2half_rn(v.x), hy = __float2half_rn(v.y);
        __half hz = __float2half_rn(v.z), hw = __float2half_rn(v.w);
        uint32_t h01 = pack_h2(v.x, v.y), h23 = pack_h2(v.z, v.w);
        uint32_t l01 = pack_h2(v.x - __half2float(hx), v.y - __half2float(hy));
        uint32_t l23 = pack_h2(v.z - __half2float(hz), v.w - __half2float(hw));
        *(uint2*)(g_xh + 4 * (size_t)i) = make_uint2(h01, h23);
        *(uint2*)(g_xl + 4 * (size_t)i) = make_uint2(l01, l23);
    } else {
        __half* dst = (which == 1) ? g_wqh : g_wfh;
        uint32_t h01 = pack_h2(v.x, v.y), h23 = pack_h2(v.z, v.w);
        *(uint2*)(dst + 4 * (size_t)i) = make_uint2(h01, h23);
    }
}

// ===========================================================================
// fp16 2-term GEMM: out[16384,N] = (Ah+Al) @ Bh + bias.
// CTA 128x128, 256 threads (8 warps, warp=32x64), BK=64,
// 3-stage cp.async ring, ONE barrier per iteration (R12-proven structure).
// MODE 0: A=x (N=3072), scatter q(hi/lo)/k(hi)/v(hi).
// MODE 1: A=ctx (N=1024), fp32 out.
// ===========================================================================
#define SA_PITCH 144                // 64 fp16 = 128B + 16 pad
#define SB_PITCH 272                // 128 fp16 = 256B + 16 pad
#define ST_AH 0
#define ST_AL (128 * SA_PITCH)              // 18432
#define ST_BH (2 * 128 * SA_PITCH)          // 36864
#define ST_SZ (ST_BH + 64 * SB_PITCH)       // 54272
#define G2_TOTAL (3 * ST_SZ)                // 162816

template <int MODE>
__global__ __launch_bounds__(256, 1) void gemm_bf(const float* __restrict__ bias,
                                                  float* __restrict__ out) {
    extern __shared__ char smem[];
    const uint32_t smb = sm_u32(smem);
    const int tid  = threadIdx.x;
    const int lane = tid & 31;
    const int wid  = tid >> 5;
    const int wm   = wid & 3;          // 4 m-blocks of 32
    const int wn   = wid >> 2;         // 2 n-blocks of 64
    const int mBase = blockIdx.y * 128;
    const int nBase = blockIdx.x * 128;
    const int ldW = (MODE == 0) ? 3072 : 1024;

    const __half* Ah = (MODE == 0) ? g_xh : g_ch;
    const __half* Al = (MODE == 0) ? g_xl : g_cl;
    const __half* Bh = (MODE == 0) ? g_wqh : g_wfh;

    float acc[2][8][4];
#pragma unroll
    for (int i = 0; i < 2; i++)
#pragma unroll
        for (int j = 0; j < 8; j++)
#pragma unroll
            for (int q = 0; q < 4; q++) acc[i][j][q] = 0.f;

    // load one BK=64 stage: A 128x64 hi+lo, B 64x128 hi.  12 cp/thread.
    auto load_stage = [&](int stage, int kc) {
        const uint32_t sb = smb + stage * ST_SZ;
        const int kOff = kc * 64;
#pragma unroll
        for (int i = 0; i < 4; i++) {
            int idx = tid + i * 256;                 // 0..1023
            int r = idx >> 3, ch = idx & 7;
            const size_t go = (size_t)(mBase + r) * 1024 + kOff + ch * 8;
            cpasync16(sb + ST_AH + r * SA_PITCH + ch * 16, Ah + go);
            cpasync16(sb + ST_AL + r * SA_PITCH + ch * 16, Al + go);
        }
#pragma unroll
        for (int i = 0; i < 4; i++) {
            int idx = tid + i * 256;                 // 0..1023
            int r = idx >> 4, ch = idx & 15;
            const size_t go = (size_t)(kOff + r) * ldW + nBase + ch * 8;
            cpasync16(sb + ST_BH + r * SB_PITCH + ch * 16, Bh + go);
        }
        CP_COMMIT();
    };

    load_stage(0, 0);
    load_stage(1, 1);

    for (int c = 0; c < 16; c++) {
        const int st = c % 3;
        if (c < 15) { CP_WAIT(1); } else { CP_WAIT(0); }
        __syncthreads();                 // stage st visible; stage (c+2)%3 free
        if (c + 2 < 16) load_stage((c + 2) % 3, c + 2);

        const uint32_t sb = smb + st * ST_SZ;
#pragma unroll
        for (int ks = 0; ks < 4; ks++) {
            const int k0 = ks * 16;
            uint32_t Ahf[2][4], Alf[2][4];
#pragma unroll
            for (int mt = 0; mt < 2; mt++) {
                uint32_t addr = sb + (uint32_t)((wm * 32 + mt * 16 + (lane & 15)) * SA_PITCH
                                                + (k0 + (lane >> 4) * 8) * 2);
                ldsm4(addr + ST_AH, Ahf[mt]);
                ldsm4(addr + ST_AL, Alf[mt]);
            }
#pragma unroll
            for (int p = 0; p < 4; p++) {
                uint32_t addr = sb + (uint32_t)((k0 + (lane & 15)) * SB_PITCH
                                                + (wn * 64 + p * 16 + (lane >> 4) * 8) * 2);
                uint32_t r[4], bh_[2][2];
                ldsm4t(addr + ST_BH, r);
                bh_[0][0] = r[0]; bh_[0][1] = r[1];
                bh_[1][0] = r[2]; bh_[1][1] = r[3];
#pragma unroll
                for (int mt = 0; mt < 2; mt++)
#pragma unroll
                    for (int nt = 0; nt < 2; nt++) {
                        float* d = acc[mt][2 * p + nt];
                        mma16816(d, Ahf[mt], bh_[nt]);
                        mma16816(d, Alf[mt], bh_[nt]);
                    }
            }
        }
        // no trailing barrier: next iteration's barrier protects stage reuse
    }

    // ---- epilogue ----
    const int rbase = mBase + wm * 32 + (lane >> 2);
    const int cbase = nBase + wn * 64 + 2 * (lane & 3);
#pragma unroll
    for (int mt = 0; mt < 2; mt++) {
#pragma unroll
        for (int nt = 0; nt < 8; nt++) {
            const int col = cbase + nt * 8;
            const float bx = __ldg(&bias[col]);
            const float by = __ldg(&bias[col + 1]);
#pragma unroll
            for (int half = 0; half < 2; half++) {
                const int row = rbase + mt * 16 + half * 8;
                float vx = acc[mt][nt][half * 2 + 0] + bx;
                float vy = acc[mt][nt][half * 2 + 1] + by;
                if (MODE == 1) {
                    *(float2*)(out + (size_t)row * 1024 + col) = make_float2(vx, vy);
                } else {
                    const int which = col >> 10;
                    const int h = (col >> 6) & 15;
                    const int d0 = col & 63;
                    const int b = row >> 10;
                    const int n_tok = row & 1023;
                    size_t idx = ((size_t)(b * NHEAD + h) * SEQ + n_tok) * DK + d0;
                    if (which == 0) {
                        __half hx = __float2half_rn(vx), hy = __float2half_rn(vy);
                        *(uint32_t*)(g_qh + idx) = pack_h2(vx, vy);
                        *(uint32_t*)(g_ql + idx) = pack_h2(vx - __half2float(hx),
                                                           vy - __half2float(hy));
                    } else {
                        __half* dst = (which == 1) ? g_kh : g_vh;
                        *(uint32_t*)(dst + idx) = pack_h2(vx, vy);
                    }
                }
            }
        }
    }
}

// ===========================================================================
// Flash attention, fp16 2-term.  CTA = 128 q rows x one (b,h), 256 threads.
// Q: hi+lo (A side).  K, V: hi only (B side).
// ===========================================================================
#define FA_PITCH  144
#define FA_QHO    0
#define FA_QLO    (128 * FA_PITCH)             // 18432
#define FA_KV0    (2 * 128 * FA_PITCH)         // 36864
#define FA_KVSZ   (2 * 64 * FA_PITCH)          // 18432 (Kh, Vh)
#define FA_KH     0
#define FA_VH     (64 * FA_PITCH)
#define FA_TOTAL  (FA_KV0 + 2 * FA_KVSZ)       // 73728

__global__ __launch_bounds__(256, 1) void flash_attn_tc() {
    extern __shared__ char smem[];
    const uint32_t smb = sm_u32(smem);
    const int tid  = threadIdx.x;
    const int lane = tid & 31;
    const int wid  = tid >> 5;
    const int qtile = blockIdx.x;
    const int bh    = blockIdx.y;

    const size_t headOff = (size_t)bh * SEQ * DK;
    const __half* Qh = g_qh + headOff + (size_t)qtile * 128 * DK;
    const __half* Ql = g_ql + headOff + (size_t)qtile * 128 * DK;
    const __half* Kh = g_kh + headOff;
    const __half* Vh = g_vh + headOff;

    {   // prologue: Q (both planes) + KV chunk 0
#pragma unroll
        for (int i = 0; i < 4; i++) {
            int idx = tid + i * 256;
            int r = idx >> 3, c16 = idx & 7;
            cpasync16(smb + FA_QHO + r * FA_PITCH + c16 * 16, (const char*)Qh + r * 128 + c16 * 16);
            cpasync16(smb + FA_QLO + r * FA_PITCH + c16 * 16, (const char*)Ql + r * 128 + c16 * 16);
        }
        const __half* src[2] = {Kh, Vh};
#pragma unroll
        for (int t2 = 0; t2 < 2; t2++) {
#pragma unroll
            for (int i = 0; i < 2; i++) {
                int idx = tid + i * 256;
                int r = idx >> 3, c16 = idx & 7;
                cpasync16(smb + FA_KV0 + t2 * (64 * FA_PITCH) + r * FA_PITCH + c16 * 16,
                          (const char*)src[t2] + r * 128 + c16 * 16);
            }
        }
        CP_COMMIT();
    }

    uint32_t QHf[4][4], QLf[4][4];
    float S[8][4];
    float O[8][4];
    float m0 = -INFINITY, m1 = -INFINITY, l0 = 0.f, l1 = 0.f;
#pragma unroll
    for (int nt = 0; nt < 8; nt++)
#pragma unroll
        for (int j = 0; j < 4; j++) O[nt][j] = 0.f;

    for (int c = 0; c < 16; c++) {
        const uint32_t kv = smb + FA_KV0 + (c & 1) * FA_KVSZ;

        if (c > 0) __syncthreads();

        if (c + 1 < 16) {
            const uint32_t nkv = smb + FA_KV0 + ((c + 1) & 1) * FA_KVSZ;
            const int rowOff = (c + 1) * 64;
            const __half* src[2] = {Kh, Vh};
#pragma unroll
            for (int t2 = 0; t2 < 2; t2++) {
#pragma unroll
                for (int i = 0; i < 2; i++) {
                    int idx = tid + i * 256;
                    int r = idx >> 3, c16 = idx & 7;
                    cpasync16(nkv + t2 * (64 * FA_PITCH) + r * FA_PITCH + c16 * 16,
                              (const char*)src[t2] + (size_t)(rowOff + r) * 128 + c16 * 16);
                }
            }
            CP_COMMIT();
            CP_WAIT(1);
        } else {
            CP_WAIT(0);
        }
        __syncthreads();

        if (c == 0) {                       // persistent Q frags
#pragma unroll
            for (int ks = 0; ks < 4; ks++) {
                uint32_t addr = smb + (uint32_t)((wid * 16 + (lane & 15)) * FA_PITCH
                                                 + (ks * 16 + (lane >> 4) * 8) * 2);
                ldsm4(addr + FA_QHO, QHf[ks]);
                ldsm4(addr + FA_QLO, QLf[ks]);
            }
        }

        // ---- S = (Qh+Ql) Kh^T ----
#pragma unroll
        for (int nt = 0; nt < 8; nt++)
#pragma unroll
            for (int j = 0; j < 4; j++) S[nt][j] = 0.f;

#pragma unroll
        for (int p = 0; p < 4; p++) {
            uint32_t bh_[4][2][2];
#pragma unroll
            for (int ks = 0; ks < 4; ks++) {
                uint32_t addr = kv + (uint32_t)((p * 16 + (lane & 15)) * FA_PITCH
                                                + (ks * 16 + (lane >> 4) * 8) * 2);
                uint32_t r[4];
                ldsm4(addr + FA_KH, r);
                bh_[ks][0][0] = r[0]; bh_[ks][0][1] = r[2];
                bh_[ks][1][0] = r[1]; bh_[ks][1][1] = r[3];
            }
#pragma unroll
            for (int ks = 0; ks < 4; ks++) {
#pragma unroll
                for (int nt = 0; nt < 2; nt++) {
                    mma16816(S[2 * p + nt], QHf[ks], bh_[ks][nt]);
                    mma16816(S[2 * p + nt], QLf[ks], bh_[ks][nt]);
                }
            }
        }

        // ---- online softmax ----
        float mx0 = -INFINITY, mx1 = -INFINITY;
#pragma unroll
        for (int nt = 0; nt < 8; nt++) {
            S[nt][0] *= 0.125f; S[nt][1] *= 0.125f;
            S[nt][2] *= 0.125f; S[nt][3] *= 0.125f;
            mx0 = fmaxf(mx0, fmaxf(S[nt][0], S[nt][1]));
            mx1 = fmaxf(mx1, fmaxf(S[nt][2], S[nt][3]));
        }
        mx0 = fmaxf(mx0, __shfl_xor_sync(0xffffffffu, mx0, 1));
        mx0 = fmaxf(mx0, __shfl_xor_sync(0xffffffffu, mx0, 2));
        mx1 = fmaxf(mx1, __shfl_xor_sync(0xffffffffu, mx1, 1));
        mx1 = fmaxf(mx1, __shfl_xor_sync(0xffffffffu, mx1, 2));
        const float nm0 = fmaxf(m0, mx0), nm1 = fmaxf(m1, mx1);
        const float a0 = __expf(m0 - nm0), a1 = __expf(m1 - nm1);
        m0 = nm0; m1 = nm1;
        float s0 = 0.f, s1 = 0.f;
#pragma unroll
        for (int nt = 0; nt < 8; nt++) {
            S[nt][0] = __expf(S[nt][0] - nm0);
            S[nt][1] = __expf(S[nt][1] - nm0);
            S[nt][2] = __expf(S[nt][2] - nm1);
            S[nt][3] = __expf(S[nt][3] - nm1);
            s0 += S[nt][0] + S[nt][1];
            s1 += S[nt][2] + S[nt][3];
        }
        s0 += __shfl_xor_sync(0xffffffffu, s0, 1);
        s0 += __shfl_xor_sync(0xffffffffu, s0, 2);
        s1 += __shfl_xor_sync(0xffffffffu, s1, 1);
        s1 += __shfl_xor_sync(0xffffffffu, s1, 2);
        l0 = l0 * a0 + s0;
        l1 = l1 * a1 + s1;
#pragma unroll
        for (int nt = 0; nt < 8; nt++) {
            O[nt][0] *= a0; O[nt][1] *= a0;
            O[nt][2] *= a1; O[nt][3] *= a1;
        }

        // ---- O += (Ph+Pl) Vh ----
#pragma unroll
        for (int kt = 0; kt < 4; kt++) {
            uint32_t ph[4], pl[4];
            {
                float e0 = S[2 * kt][0], e1 = S[2 * kt][1];
                float e2 = S[2 * kt][2], e3 = S[2 * kt][3];
                float f0 = S[2 * kt + 1][0], f1 = S[2 * kt + 1][1];
                float f2 = S[2 * kt + 1][2], f3 = S[2 * kt + 1][3];
                ph[0] = pack_h2(e0, e1); ph[1] = pack_h2(e2, e3);
                ph[2] = pack_h2(f0, f1); ph[3] = pack_h2(f2, f3);
                __half2* hp;
                hp = (__half2*)&ph[0];
                pl[0] = pack_h2(e0 - __half2float(hp->x), e1 - __half2float(hp->y));
                hp = (__half2*)&ph[1];
                pl[1] = pack_h2(e2 - __half2float(hp->x), e3 - __half2float(hp->y));
                hp = (__half2*)&ph[2];
                pl[2] = pack_h2(f0 - __half2float(hp->x), f1 - __half2float(hp->y));
                hp = (__half2*)&ph[3];
                pl[3] = pack_h2(f2 - __half2float(hp->x), f3 - __half2float(hp->y));
            }
#pragma unroll
            for (int p = 0; p < 4; p++) {
                uint32_t addr = kv + (uint32_t)((kt * 16 + (lane & 15)) * FA_PITCH
                                                + (p * 16 + (lane >> 4) * 8) * 2);
                uint32_t r[4], vh_[2][2];
                ldsm4t(addr + FA_VH, r);
                vh_[0][0] = r[0]; vh_[0][1] = r[1];
                vh_[1][0] = r[2]; vh_[1][1] = r[3];
#pragma unroll
                for (int nt = 0; nt < 2; nt++) {
                    mma16816(O[2 * p + nt], ph, vh_[nt]);
                    mma16816(O[2 * p + nt], pl, vh_[nt]);
                }
            }
        }
    }

    // ---- normalize + write ctx hi/lo (fp16) ----
    const int h = bh & 15;
    const int b = bh >> 4;
    const float i0 = 1.f / l0, i1 = 1.f / l1;
    const int r0 = qtile * 128 + wid * 16 + (lane >> 2);
    const int colb = h * 64 + 2 * (lane & 3);
#pragma unroll
    for (int nt = 0; nt < 8; nt++) {
        const int col = colb + nt * 8;
#pragma unroll
        for (int half = 0; half < 2; half++) {
            float vx = O[nt][half * 2 + 0] * (half ? i1 : i0);
            float vy = O[nt][half * 2 + 1] * (half ? i1 : i0);
            size_t idx = ((size_t)b * SEQ + r0 + half * 8) * EMB + col;
            __half hx = __float2half_rn(vx), hy = __float2half_rn(vy);
            *(uint32_t*)(g_ch + idx) = pack_h2(vx, vy);
            *(uint32_t*)(g_cl + idx) = pack_h2(vx - __half2float(hx),
                                               vy - __half2float(hy));
        }
    }
}

// ---------------------------------------------------------------------------
extern "C" void kernel_launch(void* const* d_in, const int* in_sizes, int n_in,
                              void* d_out, int out_size) {
    (void)in_sizes; (void)n_in; (void)out_size;
    const float* x     = (const float*)d_in[0];
    const float* W_qkv = (const float*)d_in[1];
    const float* b_qkv = (const float*)d_in[2];
    const float* W_fc  = (const float*)d_in[3];
    const float* b_fc  = (const float*)d_in[4];
    float* out = (float*)d_out;

    split_f32<<<(MROWS * EMB / 4 + 255) / 256, 256>>>(x, 0, MROWS * EMB / 4);
    split_f32<<<(EMB * 3072 / 4 + 255) / 256, 256>>>(W_qkv, 1, EMB * 3072 / 4);
    split_f32<<<(EMB * EMB / 4 + 255) / 256, 256>>>(W_fc, 2, EMB * EMB / 4);

    {
        cudaFuncSetAttribute(gemm_bf<0>, cudaFuncAttributeMaxDynamicSharedMemorySize, G2_TOTAL);
        dim3 grid(3072 / 128, MROWS / 128);
        gemm_bf<0><<<grid, 256, G2_TOTAL>>>(b_qkv, nullptr);
    }
    {
        cudaFuncSetAttribute(flash_attn_tc, cudaFuncAttributeMaxDynamicSharedMemorySize, FA_TOTAL);
        dim3 grid(SEQ / 128, BATCH * NHEAD);
        flash_attn_tc<<<grid, 256, FA_TOTAL>>>();
    }
    {
        cudaFuncSetAttribute(gemm_bf<1>, cudaFuncAttributeMaxDynamicSharedMemorySize, G2_TOTAL);
        dim3 grid(1024 / 128, MROWS / 128);
        gemm_bf<1><<<grid, 256, G2_TOTAL>>>(b_fc, out);
    }
}